// round 7
// baseline (speedup 1.0000x reference)
#include <cuda_runtime.h>
#include <math.h>

// ---------------------------------------------------------------------------
// MultiCrossAlign: 3-level windowed cross-attention pyramid.
//   i=3 (64x64):  fused window attn -> feat3, attmean3 ; lrelu+upsample -> ups
//   i=2 (128x128): attn -> feat2', attmean2 ; atttransfer(ta2, attmean3) ;
//                  conv3x3(concat) (+lrelu) -> cv2 ; upsample -> ups
//   i=1 (256x256): attn -> feat1' ; atttransfer(ta1, attmean2) ;
//                  conv3x3(concat) + lrelu -> d_out
// All fp32.  Conv inner loop uses packed fma.rn.f32x2 (sm_100+).
// Scratch = __device__ globals (no allocation).
// ---------------------------------------------------------------------------

__device__ float g_feat[4u * 64u * 256u * 256u];   // attention output (reused per level)
__device__ float g_ups [4u * 64u * 256u * 256u];   // upsampled features
__device__ float g_atr [4u * 64u * 256u * 256u];   // attention-transfer output
__device__ float g_cv2 [4u * 64u * 128u * 128u];   // level-2 conv output (post-lrelu)
__device__ float g_att3[256u  * 64u * 64u];        // level-3 head-mean attention
__device__ float g_att2[1024u * 64u * 64u];        // level-2 head-mean attention

__device__ __forceinline__ float lrelu_f(float x) { return x >= 0.f ? x : 0.1f * x; }

// ---- packed f32x2 helpers (Blackwell) -------------------------------------
__device__ __forceinline__ unsigned long long pack2(float lo, float hi) {
    unsigned long long r;
    asm("mov.b64 %0, {%1, %2};" : "=l"(r) : "f"(lo), "f"(hi));
    return r;
}
__device__ __forceinline__ void fma2(unsigned long long& d,
                                     unsigned long long a, unsigned long long b) {
    asm("fma.rn.f32x2 %0, %1, %2, %0;" : "+l"(d) : "l"(a), "l"(b));
}
__device__ __forceinline__ float2 unpack2(unsigned long long v) {
    float2 f;
    asm("mov.b64 {%0, %1}, %2;" : "=f"(f.x), "=f"(f.y) : "l"(v));
    return f;
}

// 64x64 @ 64x64^T tile helper: acc[16] += X[n0..n0+3][:] . Wt[o0..o0+3][:]
// X, Wt row stride 65.
__device__ __forceinline__ void mm64(const float* __restrict__ X,
                                     const float* __restrict__ Wt,
                                     float acc[16], int n0, int o0)
{
#pragma unroll 8
    for (int ch = 0; ch < 64; ch++) {
        float a0 = X[(n0 + 0) * 65 + ch];
        float a1 = X[(n0 + 1) * 65 + ch];
        float a2 = X[(n0 + 2) * 65 + ch];
        float a3 = X[(n0 + 3) * 65 + ch];
        float b0 = Wt[(o0 + 0) * 65 + ch];
        float b1 = Wt[(o0 + 1) * 65 + ch];
        float b2 = Wt[(o0 + 2) * 65 + ch];
        float b3 = Wt[(o0 + 3) * 65 + ch];
        acc[0]  += a0 * b0; acc[1]  += a0 * b1; acc[2]  += a0 * b2; acc[3]  += a0 * b3;
        acc[4]  += a1 * b0; acc[5]  += a1 * b1; acc[6]  += a1 * b2; acc[7]  += a1 * b3;
        acc[8]  += a2 * b0; acc[9]  += a2 * b1; acc[10] += a2 * b2; acc[11] += a2 * b3;
        acc[12] += a3 * b0; acc[13] += a3 * b1; acc[14] += a3 * b2; acc[15] += a3 * b3;
    }
}

// ---------------------------------------------------------------------------
// Fused window cross-attention.  One block (256 thr) per 8x8 window.
// smem buffers (each 64x65 floats):
//   A: ref window (raw) -> later V        B: ta window -> scores -> pw
//   C: weight staging (qw/kw/vw) -> AV output      D: Q -> proj staging
//   E: K          F: attmean accumulator
// ---------------------------------------------------------------------------
template <bool WRITE_ATT>
__global__ void attn_kernel(const float* __restrict__ ref, const float* __restrict__ ta,
                            const float* __restrict__ qw, const float* __restrict__ qb,
                            const float* __restrict__ kw, const float* __restrict__ kb,
                            const float* __restrict__ vw, const float* __restrict__ vb,
                            const float* __restrict__ pw, const float* __restrict__ pb,
                            const float* __restrict__ btab,
                            float* __restrict__ feat, float* __restrict__ attm,
                            int H, int W)
{
    extern __shared__ float sm[];
    float* A  = sm;
    float* Bf = A  + 4160;
    float* Cf = Bf + 4160;
    float* Df = Cf + 4160;
    float* Ef = Df + 4160;
    float* Ff = Ef + 4160;
    float* bt = Ff + 4160;   // 900: bias table
    float* bq = bt + 900;    // 64
    float* bk = bq + 64;
    float* bv = bk + 64;
    float* bp = bv + 64;
    float* msk = bp + 64;    // 64

    const int tid = threadIdx.x;
    const int nWx = W >> 3;
    const int wpb = (H >> 3) * nWx;
    const int win = blockIdx.x;
    const int b   = win / wpb;
    const int wh  = (win % wpb) / nWx;
    const int ww  = win % nWx;
    const int orow = wh * 8, ocol = ww * 8;

    // load ref/ta windows (token-major), qw, small vectors, zero Ff
    for (int idx = tid; idx < 4096; idx += 256) {
        int ch = idx >> 6, n = idx & 63;
        int off = ((b * 64 + ch) * H + orow + (n >> 3)) * W + ocol + (n & 7);
        A [n * 65 + ch] = ref[off];
        Bf[n * 65 + ch] = ta[off];
        Cf[ch * 65 + n] = qw[ch * 64 + n];   // Cf[o][c] = qw[o][c]
    }
    if (tid < 64) { bq[tid] = qb[tid]; bk[tid] = kb[tid]; bv[tid] = vb[tid]; bp[tid] = pb[tid]; }
    for (int idx = tid; idx < 900; idx += 256) bt[idx] = btab[idx];
    if (WRITE_ATT)
        for (int idx = tid; idx < 4160; idx += 256) Ff[idx] = 0.f;
    __syncthreads();

    // per-token overexposure mask
    if (tid < 64) {
        float c = 0.f;
#pragma unroll
        for (int ch = 0; ch < 64; ch++) c += (A[tid * 65 + ch] > 0.95f) ? 0.f : 1.f;
        msk[tid] = c * (1.f / 64.f);
    }
    __syncthreads();

    const int tn = tid >> 4, td = tid & 15;
    const int n0 = tn * 4, o0 = td * 4;

    // Q: q_row = 0.25 * (mask_row * (x_row @ qw^T) + qb)   [mask pre-matmul, bias unmasked]
    {
        float acc[16] = {};
        mm64(A, Cf, acc, n0, o0);
#pragma unroll
        for (int i = 0; i < 4; i++)
#pragma unroll
            for (int j = 0; j < 4; j++)
                Df[(n0 + i) * 65 + o0 + j] = 0.25f * (msk[n0 + i] * acc[i * 4 + j] + bq[o0 + j]);
    }
    __syncthreads();
#pragma unroll 4
    for (int idx = tid; idx < 4096; idx += 256) Cf[(idx >> 6) * 65 + (idx & 63)] = kw[idx];
    __syncthreads();
    // K = y @ kw^T + kb
    {
        float acc[16] = {};
        mm64(Bf, Cf, acc, n0, o0);
#pragma unroll
        for (int i = 0; i < 4; i++)
#pragma unroll
            for (int j = 0; j < 4; j++)
                Ef[(n0 + i) * 65 + o0 + j] = acc[i * 4 + j] + bk[o0 + j];
    }
    __syncthreads();
#pragma unroll 4
    for (int idx = tid; idx < 4096; idx += 256) Cf[(idx >> 6) * 65 + (idx & 63)] = vw[idx];
    __syncthreads();
    // V = y @ vw^T + vb  -> overwrite A
    {
        float acc[16] = {};
        mm64(Bf, Cf, acc, n0, o0);
        __syncthreads();
#pragma unroll
        for (int i = 0; i < 4; i++)
#pragma unroll
            for (int j = 0; j < 4; j++)
                A[(n0 + i) * 65 + o0 + j] = acc[i * 4 + j] + bv[o0 + j];
    }
    __syncthreads();

    // per-head: scores -> softmax -> AV
    for (int h = 0; h < 4; h++) {
        const int hb = h * 16;
        // scores into Bf
        {
            float acc[16] = {};
#pragma unroll
            for (int kk = 0; kk < 16; kk++) {
                float a0 = Df[(n0 + 0) * 65 + hb + kk];
                float a1 = Df[(n0 + 1) * 65 + hb + kk];
                float a2 = Df[(n0 + 2) * 65 + hb + kk];
                float a3 = Df[(n0 + 3) * 65 + hb + kk];
                float b0 = Ef[(o0 + 0) * 65 + hb + kk];
                float b1 = Ef[(o0 + 1) * 65 + hb + kk];
                float b2 = Ef[(o0 + 2) * 65 + hb + kk];
                float b3 = Ef[(o0 + 3) * 65 + hb + kk];
                acc[0]  += a0 * b0; acc[1]  += a0 * b1; acc[2]  += a0 * b2; acc[3]  += a0 * b3;
                acc[4]  += a1 * b0; acc[5]  += a1 * b1; acc[6]  += a1 * b2; acc[7]  += a1 * b3;
                acc[8]  += a2 * b0; acc[9]  += a2 * b1; acc[10] += a2 * b2; acc[11] += a2 * b3;
                acc[12] += a3 * b0; acc[13] += a3 * b1; acc[14] += a3 * b2; acc[15] += a3 * b3;
            }
#pragma unroll
            for (int i = 0; i < 4; i++) {
                int n = n0 + i, ni = n >> 3, nj = n & 7;
                float mn = msk[n];
#pragma unroll
                for (int j = 0; j < 4; j++) {
                    int m = o0 + j, mi = m >> 3, mj = m & 7;
                    int ridx = (ni - mi + 7) * 15 + (nj - mj + 7);
                    Bf[n * 65 + m] = acc[i * 4 + j] * mn * msk[m] + bt[ridx * 4 + h];
                }
            }
        }
        __syncthreads();
        // softmax rows (warp w handles rows w*8..w*8+7)
        {
            int wrp = tid >> 5, lane = tid & 31;
#pragma unroll
            for (int rr = 0; rr < 8; rr++) {
                int row = wrp * 8 + rr;
                float v0 = Bf[row * 65 + lane];
                float v1 = Bf[row * 65 + 32 + lane];
                float mx = fmaxf(v0, v1);
#pragma unroll
                for (int s = 16; s > 0; s >>= 1) mx = fmaxf(mx, __shfl_xor_sync(0xffffffffu, mx, s));
                float e0 = __expf(v0 - mx), e1 = __expf(v1 - mx);
                float sum = e0 + e1;
#pragma unroll
                for (int s = 16; s > 0; s >>= 1) sum += __shfl_xor_sync(0xffffffffu, sum, s);
                float inv = 1.f / sum;
                e0 *= inv; e1 *= inv;
                Bf[row * 65 + lane] = e0;
                Bf[row * 65 + 32 + lane] = e1;
                if (WRITE_ATT) {
                    Ff[row * 65 + lane]      += 0.25f * e0;
                    Ff[row * 65 + 32 + lane] += 0.25f * e1;
                }
            }
        }
        __syncthreads();
        // AV: Cf[n][h*16 + d]
        {
            int n = tid >> 2, c0 = (tid & 3) * 4;
            float a0 = 0.f, a1 = 0.f, a2 = 0.f, a3 = 0.f;
#pragma unroll 8
            for (int m = 0; m < 64; m++) {
                float p = Bf[n * 65 + m];
                a0 += p * A[m * 65 + hb + c0 + 0];
                a1 += p * A[m * 65 + hb + c0 + 1];
                a2 += p * A[m * 65 + hb + c0 + 2];
                a3 += p * A[m * 65 + hb + c0 + 3];
            }
            Cf[n * 65 + hb + c0 + 0] = a0;
            Cf[n * 65 + hb + c0 + 1] = a1;
            Cf[n * 65 + hb + c0 + 2] = a2;
            Cf[n * 65 + hb + c0 + 3] = a3;
        }
        __syncthreads();
    }

    // projection: out = Cf @ pw^T + pb  (stage transposed through Df)
#pragma unroll 4
    for (int idx = tid; idx < 4096; idx += 256) Bf[(idx >> 6) * 65 + (idx & 63)] = pw[idx];
    __syncthreads();
    {
        float acc[16] = {};
        mm64(Cf, Bf, acc, n0, o0);
#pragma unroll
        for (int i = 0; i < 4; i++)
#pragma unroll
            for (int j = 0; j < 4; j++)
                Df[(o0 + j) * 65 + (n0 + i)] = acc[i * 4 + j] + bp[o0 + j];
    }
    __syncthreads();
    for (int idx = tid; idx < 4096; idx += 256) {
        int ch = idx >> 6, n = idx & 63;
        feat[((b * 64 + ch) * H + orow + (n >> 3)) * W + ocol + (n & 7)] = Df[ch * 65 + n];
    }
    if (WRITE_ATT)
        for (int idx = tid; idx < 4096; idx += 256)
            attm[win * 4096 + idx] = Ff[(idx >> 6) * 65 + (idx & 63)];
}

// ---------------------------------------------------------------------------
// Attention transfer: per 16x16 fine window, per 2x2 subpixel offset (p,q):
//   out[2ni+p][2nj+q][c] = sum_m attmean[n][m] * ta[2mi+p][2mj+q][c]
// One block per window; channel chunks of 16.
// ---------------------------------------------------------------------------
__global__ void atrans_kernel(const float* __restrict__ ta, const float* __restrict__ attm,
                              float* __restrict__ out, int H, int W)
{
    extern __shared__ float sm[];
    float* A  = sm;          // 64x65 attmean
    float* tw = A + 4160;    // 256 px x 16 ch (stride 17)
    float* ow = tw + 4352;   // 256 px x 16 ch (stride 17)

    const int tid = threadIdx.x;
    const int nWx = W >> 4;
    const int wpb = (H >> 4) * nWx;
    const int win = blockIdx.x;
    const int b  = win / wpb;
    const int wh = (win % wpb) / nWx;
    const int ww = win % nWx;
    const int orow = wh * 16, ocol = ww * 16;

    for (int idx = tid; idx < 4096; idx += 256)
        A[(idx >> 6) * 65 + (idx & 63)] = attm[win * 4096 + idx];

    const int pq = tid >> 6;
    const int p = pq >> 1, q = pq & 1;
    const int n0  = ((tid >> 2) & 15) * 4;
    const int cl0 = (tid & 3) * 4;
    const int pqoff = p * 16 + q;

    for (int cc = 0; cc < 4; cc++) {
        int cb = cc * 16;
        __syncthreads();     // A ready (1st iter) / prior ow store done
        for (int idx = tid; idx < 4096; idx += 256) {
            int ch = idx >> 8, pix = idx & 255;
            tw[pix * 17 + ch] =
                ta[((b * 64 + cb + ch) * H + orow + (pix >> 4)) * W + ocol + (pix & 15)];
        }
        __syncthreads();
        float acc[16] = {};
#pragma unroll 8
        for (int m = 0; m < 64; m++) {
            int tb = ((m >> 3) * 32 + (m & 7) * 2 + pqoff) * 17 + cl0;
            float a0 = A[(n0 + 0) * 65 + m];
            float a1 = A[(n0 + 1) * 65 + m];
            float a2 = A[(n0 + 2) * 65 + m];
            float a3 = A[(n0 + 3) * 65 + m];
            float b0 = tw[tb + 0], b1 = tw[tb + 1], b2 = tw[tb + 2], b3 = tw[tb + 3];
            acc[0]  += a0 * b0; acc[1]  += a0 * b1; acc[2]  += a0 * b2; acc[3]  += a0 * b3;
            acc[4]  += a1 * b0; acc[5]  += a1 * b1; acc[6]  += a1 * b2; acc[7]  += a1 * b3;
            acc[8]  += a2 * b0; acc[9]  += a2 * b1; acc[10] += a2 * b2; acc[11] += a2 * b3;
            acc[12] += a3 * b0; acc[13] += a3 * b1; acc[14] += a3 * b2; acc[15] += a3 * b3;
        }
#pragma unroll
        for (int i = 0; i < 4; i++) {
            int n = n0 + i;
            int opix = (2 * (n >> 3) + p) * 16 + 2 * (n & 7) + q;
#pragma unroll
            for (int j = 0; j < 4; j++) ow[opix * 17 + cl0 + j] = acc[i * 4 + j];
        }
        __syncthreads();
        for (int idx = tid; idx < 4096; idx += 256) {
            int ch = idx >> 8, pix = idx & 255;
            out[((b * 64 + cb + ch) * H + orow + (pix >> 4)) * W + ocol + (pix & 15)] =
                ow[pix * 17 + ch];
        }
    }
}

// ---------------------------------------------------------------------------
// 3x3 SAME conv, Cin=192 (three 64-ch sources, concat avoided), Cout=64.
// Block: 128 thr, 32x32 tile, 8 oc; thread: 2 wide x 4 tall pixels.
// Inner math in packed fma.rn.f32x2 (horizontal pixel pair shares weight).
// Fused lrelu epilogue, STG.64 stores.
// ---------------------------------------------------------------------------
__global__ void __launch_bounds__(128)
conv3_kernel(const float* __restrict__ s0, const float* __restrict__ s1,
             const float* __restrict__ s2, const float* __restrict__ w,
             const float* __restrict__ bias, float* __restrict__ out,
             int H, int W)
{
    __shared__ float sin[4][34][36];
    __shared__ unsigned long long wsm[4][8][9];   // packed (w,w)

    const int tid = threadIdx.x;                  // 0..127
    const int b   = blockIdx.z >> 3;
    const int oc0 = (blockIdx.z & 7) * 8;
    const int oy  = blockIdx.y * 32, ox = blockIdx.x * 32;
    const int ty  = tid >> 4, tx = tid & 15;      // ty 0..7, tx 0..15
    const int py0 = 4 * ty, px0 = 2 * tx;

    unsigned long long acc[8][4] = {};            // [oc][py], lanes = (px0, px0+1)

    for (int icc = 0; icc < 48; icc++) {
#pragma unroll 4
        for (int idx = tid; idx < 4 * 34 * 34; idx += 128) {
            int sub = idx / 1156;
            int rem = idx - sub * 1156;
            int r = rem / 34, c = rem - r * 34;
            int gr = oy - 1 + r, gc = ox - 1 + c;
            int ic = icc * 4 + sub;
            const float* src = (ic < 64) ? s0 : ((ic < 128) ? s1 : s2);
            float v = 0.f;
            if (gr >= 0 && gr < H && gc >= 0 && gc < W)
                v = src[((b * 64 + (ic & 63)) * H + gr) * W + gc];
            sin[sub][r][c] = v;
        }
#pragma unroll 3
        for (int idx = tid; idx < 288; idx += 128) {
            int sub = idx / 72;
            int rem = idx - sub * 72;
            int oc = rem / 9, kk = rem - oc * 9;
            float wv = w[((oc0 + oc) * 192 + icc * 4 + sub) * 9 + kk];
            wsm[sub][oc][kk] = pack2(wv, wv);
        }
        __syncthreads();
#pragma unroll
        for (int sub = 0; sub < 4; sub++) {
            // input pairs: rows py0..py0+5, cols px0..px0+3
            unsigned long long pk[6][3];
#pragma unroll
            for (int r = 0; r < 6; r++) {
                // px0 even, sin row stride 36 even -> 8B-aligned float2 loads
                const float2* rp = (const float2*)&sin[sub][py0 + r][px0];
                float2 p01 = rp[0];
                float2 p23 = rp[1];
                pk[r][0] = pack2(p01.x, p01.y);
                pk[r][1] = pack2(p01.y, p23.x);
                pk[r][2] = pack2(p23.x, p23.y);
            }
#pragma unroll
            for (int oc = 0; oc < 8; oc++) {
                unsigned long long wq[9];
#pragma unroll
                for (int k = 0; k < 9; k++) wq[k] = wsm[sub][oc][k];
#pragma unroll
                for (int py = 0; py < 4; py++)
#pragma unroll
                    for (int dy = 0; dy < 3; dy++)
#pragma unroll
                        for (int dx = 0; dx < 3; dx++)
                            fma2(acc[oc][py], pk[py + dy][dx], wq[dy * 3 + dx]);
            }
        }
        __syncthreads();
    }
#pragma unroll
    for (int oc = 0; oc < 8; oc++) {
        float bb = bias[oc0 + oc];
#pragma unroll
        for (int py = 0; py < 4; py++) {
            float2 v = unpack2(acc[oc][py]);
            v.x = lrelu_f(v.x + bb);
            v.y = lrelu_f(v.y + bb);
            float2* dst = (float2*)&out[((b * 64 + oc0 + oc) * H + oy + py0 + py) * W + ox + px0];
            *dst = v;
        }
    }
}

// ---------------------------------------------------------------------------
// Bilinear x2 upsample (jax half-pixel, edge-renormalized == clamped taps),
// optional fused lrelu on the source.
// ---------------------------------------------------------------------------
template <bool LRELU>
__global__ void upsample_kernel(const float* __restrict__ in, float* __restrict__ out,
                                int H, int W)
{
    const int W2 = 2 * W, H2 = 2 * H;
    long total = (long)4 * 64 * H2 * W2;
    long idx = (long)blockIdx.x * blockDim.x + threadIdx.x;
    if (idx >= total) return;
    int ox = (int)(idx % W2);
    long t = idx / W2;
    int oy = (int)(t % H2);
    int bc = (int)(t / H2);
    int ty = oy >> 1, tx = ox >> 1;
    int r0, r1; float wr0, wr1;
    if (oy & 1) { r0 = ty; r1 = min(ty + 1, H - 1); wr0 = 0.75f; wr1 = 0.25f; }
    else        { r0 = max(ty - 1, 0); r1 = ty;     wr0 = 0.25f; wr1 = 0.75f; }
    int c0, c1; float wc0, wc1;
    if (ox & 1) { c0 = tx; c1 = min(tx + 1, W - 1); wc0 = 0.75f; wc1 = 0.25f; }
    else        { c0 = max(tx - 1, 0); c1 = tx;     wc0 = 0.25f; wc1 = 0.75f; }
    const float* base = in + (long)bc * H * W;
    float v00 = base[r0 * W + c0], v01 = base[r0 * W + c1];
    float v10 = base[r1 * W + c0], v11 = base[r1 * W + c1];
    if (LRELU) { v00 = lrelu_f(v00); v01 = lrelu_f(v01); v10 = lrelu_f(v10); v11 = lrelu_f(v11); }
    out[idx] = wr0 * (wc0 * v00 + wc1 * v01) + wr1 * (wc0 * v10 + wc1 * v11);
}

// ---------------------------------------------------------------------------
extern "C" void kernel_launch(void* const* d_in, const int* in_sizes, int n_in,
                              void* d_out, int out_size)
{
    const float* ref1 = (const float*)d_in[0];
    const float* ref2 = (const float*)d_in[1];
    const float* ref3 = (const float*)d_in[2];
    const float* ta1  = (const float*)d_in[3];
    const float* ta2  = (const float*)d_in[4];
    const float* ta3  = (const float*)d_in[5];
    const float* q_w  = (const float*)d_in[6];
    const float* q_b  = (const float*)d_in[7];
    const float* k_w  = (const float*)d_in[8];
    const float* k_b  = (const float*)d_in[9];
    const float* v_w  = (const float*)d_in[10];
    const float* v_b  = (const float*)d_in[11];
    const float* p_w  = (const float*)d_in[12];
    const float* p_b  = (const float*)d_in[13];
    const float* btab = (const float*)d_in[14];
    const float* fc_w = (const float*)d_in[15];
    const float* fc_b = (const float*)d_in[16];
    float* outp = (float*)d_out;

    float *feat, *ups, *atr, *cv2, *att3, *att2;
    cudaGetSymbolAddress((void**)&feat, g_feat);
    cudaGetSymbolAddress((void**)&ups,  g_ups);
    cudaGetSymbolAddress((void**)&atr,  g_atr);
    cudaGetSymbolAddress((void**)&cv2,  g_cv2);
    cudaGetSymbolAddress((void**)&att3, g_att3);
    cudaGetSymbolAddress((void**)&att2, g_att2);

    const int ATTN_SMEM = 26180 * 4;   // 104720 B
    const int ATR_SMEM  = 12864 * 4;   // 51456 B
    cudaFuncSetAttribute(attn_kernel<true>,  cudaFuncAttributeMaxDynamicSharedMemorySize, ATTN_SMEM);
    cudaFuncSetAttribute(attn_kernel<false>, cudaFuncAttributeMaxDynamicSharedMemorySize, ATTN_SMEM);
    cudaFuncSetAttribute(atrans_kernel,      cudaFuncAttributeMaxDynamicSharedMemorySize, ATR_SMEM);

    // ---- level 3 (i=3, j=2): 64x64 ----
    attn_kernel<true><<<256, 256, ATTN_SMEM>>>(
        ref3, ta3,
        q_w + 2 * 4096, q_b + 2 * 64, k_w + 2 * 4096, k_b + 2 * 64,
        v_w + 2 * 4096, v_b + 2 * 64, p_w + 2 * 4096, p_b + 2 * 64,
        btab + 2 * 900, feat, att3, 64, 64);
    upsample_kernel<true><<<(4 * 64 * 128 * 128 + 255) / 256, 256>>>(feat, ups, 64, 64);

    // ---- level 2 (i=2, j=1): 128x128 ----
    attn_kernel<true><<<1024, 256, ATTN_SMEM>>>(
        ref2, ta2,
        q_w + 4096, q_b + 64, k_w + 4096, k_b + 64,
        v_w + 4096, v_b + 64, p_w + 4096, p_b + 64,
        btab + 900, feat, att2, 128, 128);
    atrans_kernel<<<256, 256, ATR_SMEM>>>(ta2, att3, atr, 128, 128);
    conv3_kernel<<<dim3(4, 4, 32), 128>>>(feat, ups, atr,
                                          fc_w + 110592, fc_b + 64, cv2, 128, 128);
    upsample_kernel<false><<<(4 * 64 * 256 * 256 + 255) / 256, 256>>>(cv2, ups, 128, 128);

    // ---- level 1 (i=1, j=0): 256x256 ----
    attn_kernel<false><<<4096, 256, ATTN_SMEM>>>(
        ref1, ta1,
        q_w, q_b, k_w, k_b, v_w, v_b, p_w, p_b,
        btab, feat, (float*)0, 256, 256);
    atrans_kernel<<<1024, 256, ATR_SMEM>>>(ta1, att2, atr, 256, 256);
    conv3_kernel<<<dim3(8, 8, 32), 128>>>(feat, ups, atr, fc_w, fc_b, outp, 256, 256);
}